// round 5
// baseline (speedup 1.0000x reference)
#include <cuda_runtime.h>
#include <cuda_fp16.h>

#define N_NODES 50000
#define N_EDGES 625000
#define D_FEAT  128
#define K_HOPS  10
#define SZ      (N_NODES * D_FEAT)

#define SCAN_TILE 512
#define N_TILES   ((N_NODES + SCAN_TILE - 1) / SCAN_TILE)   // 98

// ---------------------------------------------------------------------------
// Scratch (device globals — no allocation allowed anywhere)
// ---------------------------------------------------------------------------
__device__ __half g_hh[(size_t)K_HOPS * SZ];  // h_k (scaled) at slot k-1, 128 MB
__device__ int    g_deg[N_NODES];
__device__ int    g_rowptr[N_NODES + 1];
__device__ int    g_cursor[N_NODES];
__device__ int    g_col[N_EDGES];
__device__ float  g_w[K_HOPS + 1];
__device__ int    g_is64;
__device__ int    g_tilesum[N_TILES];
__device__ int    g_tileoff[N_TILES];
__device__ float  g_S[K_HOPS + 1];   // S[k] = max |stored h_k| (S[0] = max|x|)
__device__ int    g_d[K_HOPS + 1];   // per-hop scale exponent d_k
__device__ int    g_maxdeg;

__device__ __forceinline__ void atomicMaxF(float* addr, float v) {
    // valid for non-negative floats
    atomicMax((int*)addr, __float_as_int(v));
}

// ---------------------------------------------------------------------------
// 0) dtype detect + softmax(att) + zero the per-launch scalars
// ---------------------------------------------------------------------------
__global__ void prep_kernel(const void* ei, const float* __restrict__ att) {
    if (threadIdx.x == 0 && blockIdx.x == 0) {
        const long long* p = (const long long*)ei;
        int is64 = 1;
        for (int i = 0; i < 64; i++) {
            long long v = p[i];
            if (v < 0 || v >= (long long)N_NODES) { is64 = 0; break; }
        }
        g_is64 = is64;

        float m = -1e30f;
        for (int i = 0; i <= K_HOPS; i++) m = fmaxf(m, att[i]);
        float e[K_HOPS + 1];
        float s = 0.f;
        for (int i = 0; i <= K_HOPS; i++) { e[i] = __expf(att[i] - m); s += e[i]; }
        float inv = 1.f / s;
        for (int i = 0; i <= K_HOPS; i++) g_w[i] = e[i] * inv;

        for (int i = 0; i <= K_HOPS; i++) { g_S[i] = 0.f; g_d[i] = 0; }
        g_maxdeg = 0;
    }
}

// max|x| -> g_S[0]
__global__ void __launch_bounds__(256)
maxx_kernel(const float* __restrict__ x) {
    float m = 0.f;
    for (int i = blockIdx.x * blockDim.x + threadIdx.x; i < SZ; i += gridDim.x * blockDim.x)
        m = fmaxf(m, fabsf(x[i]));
    for (int off = 16; off > 0; off >>= 1)
        m = fmaxf(m, __shfl_down_sync(0xFFFFFFFFu, m, off));
    if ((threadIdx.x & 31) == 0) atomicMaxF(&g_S[0], m);
}

// ---------------------------------------------------------------------------
// CSR build
// ---------------------------------------------------------------------------
__global__ void zero_deg_kernel() {
    int i = blockIdx.x * blockDim.x + threadIdx.x;
    if (i < N_NODES) g_deg[i] = 0;
}

__global__ void hist_kernel(const void* __restrict__ ei) {
    int t = blockIdx.x * blockDim.x + threadIdx.x;
    int e = t * 2;
    if (e >= N_EDGES) return;
    if (g_is64) {
        const longlong2* p = (const longlong2*)((const long long*)ei + N_EDGES);
        longlong2 d = p[t];
        atomicAdd(&g_deg[(int)d.x], 1);
        if (e + 1 < N_EDGES) atomicAdd(&g_deg[(int)d.y], 1);
    } else {
        const int2* p = (const int2*)((const int*)ei + N_EDGES);
        int2 d = p[t];
        atomicAdd(&g_deg[d.x], 1);
        if (e + 1 < N_EDGES) atomicAdd(&g_deg[d.y], 1);
    }
}

// phase 1: per-tile reduction of deg (+ global max degree)
__global__ void __launch_bounds__(SCAN_TILE)
scan_reduce_kernel() {
    __shared__ int wsum[SCAN_TILE / 32];
    int i = blockIdx.x * SCAN_TILE + threadIdx.x;
    int v = (i < N_NODES) ? g_deg[i] : 0;
    int mx = v;
    for (int off = 16; off > 0; off >>= 1) {
        v  += __shfl_down_sync(0xFFFFFFFFu, v,  off);
        mx  = max(mx, __shfl_down_sync(0xFFFFFFFFu, mx, off));
    }
    int wid = threadIdx.x >> 5;
    if ((threadIdx.x & 31) == 0) { wsum[wid] = v; atomicMax(&g_maxdeg, mx); }
    __syncthreads();
    if (wid == 0) {
        int lane = threadIdx.x & 31;
        int s = (lane < SCAN_TILE / 32) ? wsum[lane] : 0;
        for (int off = 16; off > 0; off >>= 1)
            s += __shfl_down_sync(0xFFFFFFFFu, s, off);
        if (lane == 0) g_tilesum[blockIdx.x] = s;
    }
}

// phase 2: exclusive scan of tile sums
__global__ void scan_tiles_kernel() {
    __shared__ int wtot[4];
    int tid  = threadIdx.x;
    int lane = tid & 31;
    int wid  = tid >> 5;
    int v = (tid < N_TILES) ? g_tilesum[tid] : 0;
    int incl = v;
    for (int off = 1; off < 32; off <<= 1) {
        int u = __shfl_up_sync(0xFFFFFFFFu, incl, off);
        if (lane >= off) incl += u;
    }
    if (lane == 31) wtot[wid] = incl;
    __syncthreads();
    int base = 0;
    for (int w = 0; w < wid; w++) base += wtot[w];
    int excl = base + incl - v;
    if (tid < N_TILES) g_tileoff[tid] = excl;
    if (tid == N_TILES - 1) g_rowptr[N_NODES] = excl + v;
}

// phase 3: per-tile exclusive scan + tile offset -> rowptr/cursor
__global__ void __launch_bounds__(SCAN_TILE)
scan_final_kernel() {
    __shared__ int wtot[SCAN_TILE / 32];
    int i    = blockIdx.x * SCAN_TILE + threadIdx.x;
    int lane = threadIdx.x & 31;
    int wid  = threadIdx.x >> 5;

    int v = (i < N_NODES) ? g_deg[i] : 0;
    int incl = v;
    for (int off = 1; off < 32; off <<= 1) {
        int u = __shfl_up_sync(0xFFFFFFFFu, incl, off);
        if (lane >= off) incl += u;
    }
    if (lane == 31) wtot[wid] = incl;
    __syncthreads();
    if (wid == 0) {
        int s = (lane < SCAN_TILE / 32) ? wtot[lane] : 0;
        int si = s;
        for (int off = 1; off < 32; off <<= 1) {
            int u = __shfl_up_sync(0xFFFFFFFFu, si, off);
            if (lane >= off) si += u;
        }
        if (lane < SCAN_TILE / 32) wtot[lane] = si - s;
    }
    __syncthreads();

    if (i < N_NODES) {
        int excl = g_tileoff[blockIdx.x] + wtot[wid] + incl - v;
        g_rowptr[i] = excl;
        g_cursor[i] = excl;
    }
}

__global__ void scatter_kernel(const void* __restrict__ ei) {
    int t = blockIdx.x * blockDim.x + threadIdx.x;
    int e = t * 2;
    if (e >= N_EDGES) return;
    if (g_is64) {
        const long long* p = (const long long*)ei;
        longlong2 sp = ((const longlong2*)p)[t];
        longlong2 dp = ((const longlong2*)(p + N_EDGES))[t];
        int q0 = atomicAdd(&g_cursor[(int)dp.x], 1);
        g_col[q0] = (int)sp.x;
        if (e + 1 < N_EDGES) {
            int q1 = atomicAdd(&g_cursor[(int)dp.y], 1);
            g_col[q1] = (int)sp.y;
        }
    } else {
        const int* p = (const int*)ei;
        int2 sp = ((const int2*)p)[t];
        int2 dp = ((const int2*)(p + N_EDGES))[t];
        int q0 = atomicAdd(&g_cursor[dp.x], 1);
        g_col[q0] = sp.x;
        if (e + 1 < N_EDGES) {
            int q1 = atomicAdd(&g_cursor[dp.y], 1);
            g_col[q1] = sp.y;
        }
    }
}

// ---------------------------------------------------------------------------
// propagation hop k (warp-per-node), fp16 storage, exact power-of-2 scaling:
//   stored_k = (A * stored_{k-1}) * 2^{-d_k}
//   d_k chosen from the guaranteed bound maxdeg * S[k-1] so fp16 never
//   overflows; power-of-2 scaling is exact (no rounding error added).
// hop 1 reads x in fp32 (stored_0 = x, S[0] = max|x|).
// Lane L owns features [4L, 4L+4): 8B load per lane = 256B per edge row.
// ---------------------------------------------------------------------------
__global__ void __launch_bounds__(512)
prop_kernel(const float* __restrict__ x, int k) {
    const int gwarp = (blockIdx.x * blockDim.x + threadIdx.x) >> 5;
    const int lane  = threadIdx.x & 31;
    const int wid   = threadIdx.x >> 5;
    __shared__ float smax[16];

    float4 a0 = make_float4(0.f, 0.f, 0.f, 0.f);
    float4 a1 = make_float4(0.f, 0.f, 0.f, 0.f);

    if (gwarp < N_NODES) {
        const int beg = g_rowptr[gwarp];
        const int end = g_rowptr[gwarp + 1];
        int e = beg;
        if (k == 1) {
            const float4* __restrict__ hi = (const float4*)x;
            for (; e + 4 <= end; e += 4) {
                int s0 = g_col[e], s1 = g_col[e+1], s2 = g_col[e+2], s3 = g_col[e+3];
                float4 v0 = __ldg(&hi[s0 * 32 + lane]);
                float4 v1 = __ldg(&hi[s1 * 32 + lane]);
                float4 v2 = __ldg(&hi[s2 * 32 + lane]);
                float4 v3 = __ldg(&hi[s3 * 32 + lane]);
                a0.x += v0.x; a0.y += v0.y; a0.z += v0.z; a0.w += v0.w;
                a1.x += v1.x; a1.y += v1.y; a1.z += v1.z; a1.w += v1.w;
                a0.x += v2.x; a0.y += v2.y; a0.z += v2.z; a0.w += v2.w;
                a1.x += v3.x; a1.y += v3.y; a1.z += v3.z; a1.w += v3.w;
            }
            for (; e < end; e++) {
                float4 v = __ldg(&hi[g_col[e] * 32 + lane]);
                a0.x += v.x; a0.y += v.y; a0.z += v.z; a0.w += v.w;
            }
        } else {
            const __half2* __restrict__ hi =
                (const __half2*)(g_hh + (size_t)(k - 2) * SZ);
            // lane reads half2 pair at indices 2*(s*32+lane), +1  (8 bytes)
            const uint2* __restrict__ hv = (const uint2*)hi;
            for (; e + 4 <= end; e += 4) {
                int s0 = g_col[e], s1 = g_col[e+1], s2 = g_col[e+2], s3 = g_col[e+3];
                uint2 u0 = __ldg(&hv[s0 * 32 + lane]);
                uint2 u1 = __ldg(&hv[s1 * 32 + lane]);
                uint2 u2 = __ldg(&hv[s2 * 32 + lane]);
                uint2 u3 = __ldg(&hv[s3 * 32 + lane]);
                float2 p;
                p = __half22float2(*(__half2*)&u0.x); a0.x += p.x; a0.y += p.y;
                p = __half22float2(*(__half2*)&u0.y); a0.z += p.x; a0.w += p.y;
                p = __half22float2(*(__half2*)&u1.x); a1.x += p.x; a1.y += p.y;
                p = __half22float2(*(__half2*)&u1.y); a1.z += p.x; a1.w += p.y;
                p = __half22float2(*(__half2*)&u2.x); a0.x += p.x; a0.y += p.y;
                p = __half22float2(*(__half2*)&u2.y); a0.z += p.x; a0.w += p.y;
                p = __half22float2(*(__half2*)&u3.x); a1.x += p.x; a1.y += p.y;
                p = __half22float2(*(__half2*)&u3.y); a1.z += p.x; a1.w += p.y;
            }
            for (; e < end; e++) {
                uint2 u = __ldg(&hv[g_col[e] * 32 + lane]);
                float2 p;
                p = __half22float2(*(__half2*)&u.x); a0.x += p.x; a0.y += p.y;
                p = __half22float2(*(__half2*)&u.y); a0.z += p.x; a0.w += p.y;
            }
        }
    }
    float4 acc = make_float4(a0.x + a1.x, a0.y + a1.y, a0.z + a1.z, a0.w + a1.w);

    // deterministic per-hop scale from previous hop's measured max
    float bound = g_S[k - 1] * (float)g_maxdeg;
    int d = 0;
    if (bound > 32768.f) d = (int)ceilf(log2f(bound * (1.f / 32768.f)));
    float sc = exp2f(-(float)d);          // exact power of 2
    acc.x *= sc; acc.y *= sc; acc.z *= sc; acc.w *= sc;

    // track max |stored_k|
    float m = fmaxf(fmaxf(fabsf(acc.x), fabsf(acc.y)),
                    fmaxf(fabsf(acc.z), fabsf(acc.w)));
    for (int off = 16; off > 0; off >>= 1)
        m = fmaxf(m, __shfl_down_sync(0xFFFFFFFFu, m, off));
    if (lane == 0) smax[wid] = m;
    __syncthreads();
    if (threadIdx.x == 0) {
        float bm = 0.f;
        for (int w = 0; w < 16; w++) bm = fmaxf(bm, smax[w]);
        atomicMaxF(&g_S[k], bm);
        if (blockIdx.x == 0) g_d[k] = d;
    }

    if (gwarp < N_NODES) {
        __half2* ho = (__half2*)(g_hh + (size_t)(k - 1) * SZ);
        uint2 st;
        __half2 h01 = __floats2half2_rn(acc.x, acc.y);
        __half2 h23 = __floats2half2_rn(acc.z, acc.w);
        st.x = *(unsigned*)&h01;
        st.y = *(unsigned*)&h23;
        ((uint2*)ho)[gwarp * 32 + lane] = st;
    }
}

// ---------------------------------------------------------------------------
// final combine: out = w0*x + sum_k w_k * 2^{E_k} * stored_k,  E_k = sum d_j
// ---------------------------------------------------------------------------
__global__ void __launch_bounds__(256)
combine_kernel(const float* __restrict__ x, float* __restrict__ out) {
    int i = blockIdx.x * blockDim.x + threadIdx.x;   // uint2 / float4 index
    if (i >= SZ / 4) return;

    float f[K_HOPS + 1];
    {
        int E = 0;
        for (int k = 1; k <= K_HOPS; k++) {
            E += g_d[k];
            f[k] = g_w[k] * exp2f((float)E);
        }
        f[0] = g_w[0];
    }

    float4 xv = ((const float4*)x)[i];
    float4 r;
    r.x = f[0] * xv.x; r.y = f[0] * xv.y; r.z = f[0] * xv.z; r.w = f[0] * xv.w;

#pragma unroll
    for (int k = 1; k <= K_HOPS; k++) {
        uint2 u = __ldg(&((const uint2*)(g_hh + (size_t)(k - 1) * SZ))[i]);
        float2 p0 = __half22float2(*(__half2*)&u.x);
        float2 p1 = __half22float2(*(__half2*)&u.y);
        r.x += f[k] * p0.x; r.y += f[k] * p0.y;
        r.z += f[k] * p1.x; r.w += f[k] * p1.y;
    }
    ((float4*)out)[i] = r;
}

// ---------------------------------------------------------------------------
// launch
// ---------------------------------------------------------------------------
extern "C" void kernel_launch(void* const* d_in, const int* in_sizes, int n_in,
                              void* d_out, int out_size) {
    const float* x   = nullptr;
    const float* att = nullptr;
    const void*  ei  = nullptr;
    for (int i = 0; i < n_in; i++) {
        if (in_sizes[i] == SZ)               x   = (const float*)d_in[i];
        else if (in_sizes[i] == K_HOPS + 1)  att = (const float*)d_in[i];
        else if (in_sizes[i] == 2 * N_EDGES) ei  = d_in[i];
    }
    float* out = (float*)d_out;

    prep_kernel<<<1, 32>>>(ei, att);
    maxx_kernel<<<296, 256>>>(x);

    zero_deg_kernel<<<(N_NODES + 255) / 256, 256>>>();
    hist_kernel<<<((N_EDGES + 1) / 2 + 255) / 256, 256>>>(ei);
    scan_reduce_kernel<<<N_TILES, SCAN_TILE>>>();
    scan_tiles_kernel<<<1, 128>>>();
    scan_final_kernel<<<N_TILES, SCAN_TILE>>>();
    scatter_kernel<<<((N_EDGES + 1) / 2 + 255) / 256, 256>>>(ei);

    const int prop_blocks = (N_NODES * 32 + 511) / 512;
    for (int k = 1; k <= K_HOPS; k++) {
        prop_kernel<<<prop_blocks, 512>>>(x, k);
    }

    combine_kernel<<<(SZ / 4 + 255) / 256, 256>>>(x, out);
}